// round 3
// baseline (speedup 1.0000x reference)
#include <cuda_runtime.h>
#include <cuda_bf16.h>
#include <cstdint>

#define STEPS  30
#define HIDDEN 32
#define NPAIR  (HIDDEN / 2)
#define TPB    128
#define EPT    2                 // elements per thread
#define EPC    (TPB * EPT)       // elements per CTA = 256

// ---------- packed f32x2 helpers (Blackwell sm_100+) ----------
__device__ __forceinline__ unsigned long long pack2(float lo, float hi) {
    unsigned long long r;
    asm("mov.b64 %0, {%1, %2};" : "=l"(r) : "f"(lo), "f"(hi));
    return r;
}
__device__ __forceinline__ void unpack2(unsigned long long v, float& lo, float& hi) {
    asm("mov.b64 {%0, %1}, %2;" : "=f"(lo), "=f"(hi) : "l"(v));
}
__device__ __forceinline__ unsigned long long fma2(unsigned long long a,
                                                   unsigned long long b,
                                                   unsigned long long c) {
    unsigned long long d;
    asm("fma.rn.f32x2 %0, %1, %2, %3;" : "=l"(d) : "l"(a), "l"(b), "l"(c));
    return d;
}
__device__ __forceinline__ unsigned long long add2(unsigned long long a,
                                                   unsigned long long b) {
    unsigned long long d;
    asm("add.rn.f32x2 %0, %1, %2;" : "=l"(d) : "l"(a), "l"(b));
    return d;
}
__device__ __forceinline__ unsigned long long relu2(unsigned long long v) {
    float lo, hi;
    unpack2(v, lo, hi);
    lo = fmaxf(lo, 0.0f);
    hi = fmaxf(hi, 0.0f);
    return pack2(lo, hi);
}

__global__ void __launch_bounds__(TPB, 2)
rhm_kernel(const float* __restrict__ S,
           const float* __restrict__ W1,
           const float* __restrict__ b1,
           const float* __restrict__ W2,
           const float* __restrict__ b2,
           const float* __restrict__ a_init,
           float* __restrict__ out,
           int B)
{
    // Staging: S rows on entry, d outputs on exit. Stride 31 -> conflict-free.
    __shared__ float sbuf[EPC][STEPS + 1];

    const int tid = threadIdx.x;
    const long long base = (long long)blockIdx.x * EPC;
    const int nvalid = (int)min((long long)EPC, (long long)B - base);
    const int ntot   = nvalid * STEPS;

    // ---- coalesced stage-in of S (256 rows x 30 floats) ----
    {
        const float* Sblk = S + base * STEPS;
        #pragma unroll
        for (int k = 0; k < EPT * STEPS; ++k) {
            int i = k * TPB + tid;
            if (i < ntot) {
                int e  = i / STEPS;
                int st = i - e * STEPS;
                sbuf[e][st] = Sblk[i];
            }
        }
    }

    // ---- all weights register-resident (R1 layout: latency off the loop) ----
    unsigned long long w0p[NPAIR], w1p[NPAIR], w2p[NPAIR], b1p[NPAIR], wop[NPAIR];
    {
        const float2* W1f2 = reinterpret_cast<const float2*>(W1);  // (3,32)
        const float2* b1f2 = reinterpret_cast<const float2*>(b1);
        const float2* W2f2 = reinterpret_cast<const float2*>(W2);  // (32,1)
        #pragma unroll
        for (int j = 0; j < NPAIR; ++j) {
            float2 a = W1f2[j];              w0p[j] = pack2(a.x, a.y);
            float2 bb = W1f2[NPAIR + j];     w1p[j] = pack2(bb.x, bb.y);
            float2 c = W1f2[2 * NPAIR + j];  w2p[j] = pack2(c.x, c.y);
            float2 dd = b1f2[j];             b1p[j] = pack2(dd.x, dd.y);
            float2 e = W2f2[j];              wop[j] = pack2(e.x, e.y);
        }
    }
    const float bias2 = b2[0];
    const float dinit = a_init[0];

    float h0 = 0.0f, h1 = 0.0f;
    float d0 = dinit, d1 = dinit;

    __syncthreads();

    const bool act0 = (tid < nvalid);
    const bool act1 = (TPB + tid < nvalid);
    const int  r0 = tid;          // sbuf row, element 0
    const int  r1 = TPB + tid;    // sbuf row, element 1

    #pragma unroll 1
    for (int t = 0; t < STEPS; ++t) {
        float sa = act0 ? sbuf[r0][t] : 0.0f;
        float sb = act1 ? sbuf[r1][t] : 0.0f;

        unsigned long long s2a = pack2(sa, sa), s2b = pack2(sb, sb);
        unsigned long long d2a = pack2(d0, d0), d2b = pack2(d1, d1);
        unsigned long long h2a = pack2(h0, h0), h2b = pack2(h1, h1);

        unsigned long long accA0 = 0ull, accA1 = 0ull;
        unsigned long long accB0 = 0ull, accB1 = 0ull;

        #pragma unroll
        for (int j = 0; j < NPAIR; ++j) {
            // element 0
            unsigned long long pa = fma2(s2a, w0p[j], b1p[j]);
            // element 1 (independent chain, interleaved for ILP)
            unsigned long long pb = fma2(s2b, w0p[j], b1p[j]);
            pa = fma2(d2a, w1p[j], pa);
            pb = fma2(d2b, w1p[j], pb);
            pa = fma2(h2a, w2p[j], pa);
            pb = fma2(h2b, w2p[j], pb);
            pa = relu2(pa);
            pb = relu2(pb);
            if (j & 1) { accA1 = fma2(pa, wop[j], accA1); accB1 = fma2(pb, wop[j], accB1); }
            else       { accA0 = fma2(pa, wop[j], accA0); accB0 = fma2(pb, wop[j], accB0); }
        }

        float la, ha, lb, hb;
        unpack2(add2(accA0, accA1), la, ha);
        unpack2(add2(accB0, accB1), lb, hb);
        float dn0 = la + ha + bias2;
        float dn1 = lb + hb + bias2;

        h0 = 0.8f * h0 + 0.2f * dn0;
        h1 = 0.8f * h1 + 0.2f * dn1;
        d0 = dn0;
        d1 = dn1;
        if (act0) sbuf[r0][t] = dn0;
        if (act1) sbuf[r1][t] = dn1;
    }

    __syncthreads();

    // ---- coalesced flush ----
    {
        float* Oblk = out + base * STEPS;
        #pragma unroll
        for (int k = 0; k < EPT * STEPS; ++k) {
            int i = k * TPB + tid;
            if (i < ntot) {
                int e  = i / STEPS;
                int st = i - e * STEPS;
                Oblk[i] = sbuf[e][st];
            }
        }
    }
}

extern "C" void kernel_launch(void* const* d_in, const int* in_sizes, int n_in,
                              void* d_out, int out_size)
{
    const float* S      = (const float*)d_in[0];
    const float* W1     = (const float*)d_in[1];
    const float* b1     = (const float*)d_in[2];
    const float* W2     = (const float*)d_in[3];
    const float* b2     = (const float*)d_in[4];
    const float* a_init = (const float*)d_in[5];
    float* out = (float*)d_out;

    int B = in_sizes[0] / STEPS;
    int grid = (B + EPC - 1) / EPC;
    rhm_kernel<<<grid, TPB>>>(S, W1, b1, W2, b2, a_init, out, B);
}

// round 4
// speedup vs baseline: 1.3510x; 1.3510x over previous
#include <cuda_runtime.h>
#include <cuda_bf16.h>
#include <cstdint>

#define STEPS  30
#define HIDDEN 32
#define TPB    128
#define WARPS  (TPB / 32)        // 4
#define EPW    16                // elements per warp (2 lanes per element)
#define EPC    (WARPS * EPW)     // 64 elements per CTA
#define HPAIRS 8                 // hidden pairs per lane (16 units)

// ---------- packed f32x2 helpers (Blackwell sm_100+) ----------
__device__ __forceinline__ unsigned long long pack2(float lo, float hi) {
    unsigned long long r;
    asm("mov.b64 %0, {%1, %2};" : "=l"(r) : "f"(lo), "f"(hi));
    return r;
}
__device__ __forceinline__ void unpack2(unsigned long long v, float& lo, float& hi) {
    asm("mov.b64 {%0, %1}, %2;" : "=f"(lo), "=f"(hi) : "l"(v));
}
__device__ __forceinline__ unsigned long long fma2(unsigned long long a,
                                                   unsigned long long b,
                                                   unsigned long long c) {
    unsigned long long d;
    asm("fma.rn.f32x2 %0, %1, %2, %3;" : "=l"(d) : "l"(a), "l"(b), "l"(c));
    return d;
}
__device__ __forceinline__ unsigned long long add2(unsigned long long a,
                                                   unsigned long long b) {
    unsigned long long d;
    asm("add.rn.f32x2 %0, %1, %2;" : "=l"(d) : "l"(a), "l"(b));
    return d;
}
__device__ __forceinline__ unsigned long long relu2(unsigned long long v) {
    float lo, hi;
    unpack2(v, lo, hi);
    lo = fmaxf(lo, 0.0f);
    hi = fmaxf(hi, 0.0f);
    return pack2(lo, hi);
}

__global__ void __launch_bounds__(TPB, 4)
rhm_kernel(const float* __restrict__ S,
           const float* __restrict__ W1,
           const float* __restrict__ b1,
           const float* __restrict__ W2,
           const float* __restrict__ b2,
           const float* __restrict__ a_init,
           float* __restrict__ out,
           int B)
{
    // Staging: S rows on entry, d outputs on exit. Stride 31 -> conflict-free.
    __shared__ float sbuf[EPC][STEPS + 1];

    const int tid  = threadIdx.x;
    const int lane = tid & 31;
    const int wid  = tid >> 5;
    const int half = lane & 1;            // which 16 hidden units this lane owns
    const int e    = wid * EPW + (lane >> 1);  // element row in sbuf (0..63)

    const long long base = (long long)blockIdx.x * EPC;
    const int nvalid = (int)min((long long)EPC, (long long)B - base);
    const int ntot   = nvalid * STEPS;

    // ---- coalesced stage-in of S (64 rows x 30 floats = 1920 = 15*128) ----
    {
        const float* Sblk = S + base * STEPS;
        #pragma unroll
        for (int k = 0; k < (EPC * STEPS) / TPB; ++k) {
            int i = k * TPB + tid;
            if (i < ntot) {
                int el = i / STEPS;
                int st = i - el * STEPS;
                sbuf[el][st] = Sblk[i];
            }
        }
    }

    // ---- this lane's half of the weights: units [half*16, half*16+16) ----
    unsigned long long w0p[HPAIRS], w1p[HPAIRS], w2p[HPAIRS], b1p[HPAIRS], wop[HPAIRS];
    {
        const float2* W1f2 = reinterpret_cast<const float2*>(W1);  // (3,32) row-major
        const float2* b1f2 = reinterpret_cast<const float2*>(b1);
        const float2* W2f2 = reinterpret_cast<const float2*>(W2);  // (32,1)
        const int pbase = half * HPAIRS;
        #pragma unroll
        for (int j = 0; j < HPAIRS; ++j) {
            int p = pbase + j;
            float2 a = W1f2[p];       w0p[j] = pack2(a.x, a.y);   // W1[0]
            float2 bb = W1f2[16 + p]; w1p[j] = pack2(bb.x, bb.y); // W1[1]
            float2 c = W1f2[32 + p];  w2p[j] = pack2(c.x, c.y);   // W1[2]
            float2 dd = b1f2[p];      b1p[j] = pack2(dd.x, dd.y);
            float2 ee = W2f2[p];      wop[j] = pack2(ee.x, ee.y);
        }
    }
    const float bias2 = b2[0];

    float h = 0.0f;
    float d = a_init[0];

    __syncthreads();

    #pragma unroll 1
    for (int t = 0; t < STEPS; ++t) {
        float s = sbuf[e][t];                 // broadcast within lane pair
        unsigned long long s2 = pack2(s, s);
        unsigned long long d2 = pack2(d, d);
        unsigned long long h2 = pack2(h, h);

        unsigned long long acc0 = 0ull, acc1 = 0ull;

        #pragma unroll
        for (int j = 0; j < HPAIRS; ++j) {
            unsigned long long p = fma2(s2, w0p[j], b1p[j]);
            p = fma2(d2, w1p[j], p);
            p = fma2(h2, w2p[j], p);
            p = relu2(p);
            if (j & 1) acc1 = fma2(p, wop[j], acc1);
            else       acc0 = fma2(p, wop[j], acc0);
        }

        float lo, hi;
        unpack2(add2(acc0, acc1), lo, hi);
        float mine  = lo + hi;                                    // this lane's 16-unit dot
        float other = __shfl_xor_sync(0xffffffffu, mine, 1);      // partner's half
        float dnew  = mine + other + bias2;

        h = 0.8f * h + 0.2f * dnew;
        d = dnew;
        if (half == 0) sbuf[e][t] = dnew;     // one writer per element
    }

    __syncthreads();

    // ---- coalesced flush ----
    {
        float* Oblk = out + base * STEPS;
        #pragma unroll
        for (int k = 0; k < (EPC * STEPS) / TPB; ++k) {
            int i = k * TPB + tid;
            if (i < ntot) {
                int el = i / STEPS;
                int st = i - el * STEPS;
                Oblk[i] = sbuf[el][st];
            }
        }
    }
}

extern "C" void kernel_launch(void* const* d_in, const int* in_sizes, int n_in,
                              void* d_out, int out_size)
{
    const float* S      = (const float*)d_in[0];
    const float* W1     = (const float*)d_in[1];
    const float* b1     = (const float*)d_in[2];
    const float* W2     = (const float*)d_in[3];
    const float* b2     = (const float*)d_in[4];
    const float* a_init = (const float*)d_in[5];
    float* out = (float*)d_out;

    int B = in_sizes[0] / STEPS;
    int grid = (B + EPC - 1) / EPC;
    rhm_kernel<<<grid, TPB>>>(S, W1, b1, W2, b2, a_init, out, B);
}

// round 5
// speedup vs baseline: 1.3705x; 1.0144x over previous
#include <cuda_runtime.h>
#include <cuda_bf16.h>
#include <cstdint>

#define STEPS  30
#define HIDDEN 32
#define TPB    128
#define WARPS  (TPB / 32)        // 4
#define EPT    2                 // elements per thread(-pair)
#define EPW    (16 * EPT)        // 32 elements per warp
#define EPC    (WARPS * EPW)     // 128 elements per CTA
#define HPAIRS 8                 // hidden pairs per lane (16 units)

// ---------- packed f32x2 helpers (Blackwell sm_100+) ----------
__device__ __forceinline__ unsigned long long pack2(float lo, float hi) {
    unsigned long long r;
    asm("mov.b64 %0, {%1, %2};" : "=l"(r) : "f"(lo), "f"(hi));
    return r;
}
__device__ __forceinline__ void unpack2(unsigned long long v, float& lo, float& hi) {
    asm("mov.b64 {%0, %1}, %2;" : "=f"(lo), "=f"(hi) : "l"(v));
}
__device__ __forceinline__ unsigned long long fma2(unsigned long long a,
                                                   unsigned long long b,
                                                   unsigned long long c) {
    unsigned long long d;
    asm("fma.rn.f32x2 %0, %1, %2, %3;" : "=l"(d) : "l"(a), "l"(b), "l"(c));
    return d;
}
__device__ __forceinline__ unsigned long long add2(unsigned long long a,
                                                   unsigned long long b) {
    unsigned long long d;
    asm("add.rn.f32x2 %0, %1, %2;" : "=l"(d) : "l"(a), "l"(b));
    return d;
}
__device__ __forceinline__ unsigned long long relu2(unsigned long long v) {
    float lo, hi;
    unpack2(v, lo, hi);
    lo = fmaxf(lo, 0.0f);
    hi = fmaxf(hi, 0.0f);
    return pack2(lo, hi);
}

__global__ void __launch_bounds__(TPB, 4)
rhm_kernel(const float* __restrict__ S,
           const float* __restrict__ W1,
           const float* __restrict__ b1,
           const float* __restrict__ W2,
           const float* __restrict__ b2,
           const float* __restrict__ a_init,
           float* __restrict__ out,
           int B)
{
    // Staging: S rows on entry, d outputs on exit. Stride 31 -> conflict-free.
    __shared__ float sbuf[EPC][STEPS + 1];

    const int tid  = threadIdx.x;
    const int lane = tid & 31;
    const int wid  = tid >> 5;
    const int half = lane & 1;                  // which 16 hidden units this lane owns
    const int e0   = wid * EPW + (lane >> 1);   // element A row
    const int e1   = e0 + 16;                   // element B row

    const long long base = (long long)blockIdx.x * EPC;
    const int nvalid = (int)min((long long)EPC, (long long)B - base);
    const int ntot   = nvalid * STEPS;

    // ---- coalesced stage-in of S (128 rows x 30 floats) ----
    {
        const float* Sblk = S + base * STEPS;
        #pragma unroll
        for (int k = 0; k < (EPC * STEPS) / TPB; ++k) {
            int i = k * TPB + tid;
            if (i < ntot) {
                int el = i / STEPS;
                int st = i - el * STEPS;
                sbuf[el][st] = Sblk[i];
            }
        }
    }

    // ---- this lane's half of the weights: units [half*16, half*16+16) ----
    unsigned long long w0p[HPAIRS], w1p[HPAIRS], w2p[HPAIRS], b1p[HPAIRS], wop[HPAIRS];
    {
        const float2* W1f2 = reinterpret_cast<const float2*>(W1);  // (3,32) row-major
        const float2* b1f2 = reinterpret_cast<const float2*>(b1);
        const float2* W2f2 = reinterpret_cast<const float2*>(W2);  // (32,1)
        const int pbase = half * HPAIRS;
        #pragma unroll
        for (int j = 0; j < HPAIRS; ++j) {
            int p = pbase + j;
            float2 a = W1f2[p];       w0p[j] = pack2(a.x, a.y);
            float2 bb = W1f2[16 + p]; w1p[j] = pack2(bb.x, bb.y);
            float2 c = W1f2[32 + p];  w2p[j] = pack2(c.x, c.y);
            float2 dd = b1f2[p];      b1p[j] = pack2(dd.x, dd.y);
            float2 ee = W2f2[p];      wop[j] = pack2(ee.x, ee.y);
        }
    }
    const float bias2 = b2[0];
    const float dinit = a_init[0];

    float hA = 0.0f, hB = 0.0f;
    float dA = dinit, dB = dinit;

    __syncthreads();

    #pragma unroll 1
    for (int t = 0; t < STEPS; ++t) {
        float sA = sbuf[e0][t];
        float sB = sbuf[e1][t];

        unsigned long long s2A = pack2(sA, sA), s2B = pack2(sB, sB);
        unsigned long long d2A = pack2(dA, dA), d2B = pack2(dB, dB);
        unsigned long long h2A = pack2(hA, hA), h2B = pack2(hB, hB);

        unsigned long long accA0 = 0ull, accA1 = 0ull;
        unsigned long long accB0 = 0ull, accB1 = 0ull;

        #pragma unroll
        for (int j = 0; j < HPAIRS; ++j) {
            unsigned long long pA = fma2(s2A, w0p[j], b1p[j]);
            unsigned long long pB = fma2(s2B, w0p[j], b1p[j]);
            pA = fma2(d2A, w1p[j], pA);
            pB = fma2(d2B, w1p[j], pB);
            pA = fma2(h2A, w2p[j], pA);
            pB = fma2(h2B, w2p[j], pB);
            pA = relu2(pA);
            pB = relu2(pB);
            if (j & 1) { accA1 = fma2(pA, wop[j], accA1); accB1 = fma2(pB, wop[j], accB1); }
            else       { accA0 = fma2(pA, wop[j], accA0); accB0 = fma2(pB, wop[j], accB0); }
        }

        float loA, hiA, loB, hiB;
        unpack2(add2(accA0, accA1), loA, hiA);
        unpack2(add2(accB0, accB1), loB, hiB);
        float mineA = loA + hiA;
        float mineB = loB + hiB;
        float othA = __shfl_xor_sync(0xffffffffu, mineA, 1);
        float othB = __shfl_xor_sync(0xffffffffu, mineB, 1);
        float dnA = mineA + othA + bias2;
        float dnB = mineB + othB + bias2;

        hA = 0.8f * hA + 0.2f * dnA;
        hB = 0.8f * hB + 0.2f * dnB;
        dA = dnA;
        dB = dnB;
        if (half == 0) {
            sbuf[e0][t] = dnA;
            sbuf[e1][t] = dnB;
        }
    }

    __syncthreads();

    // ---- coalesced flush ----
    {
        float* Oblk = out + base * STEPS;
        #pragma unroll
        for (int k = 0; k < (EPC * STEPS) / TPB; ++k) {
            int i = k * TPB + tid;
            if (i < ntot) {
                int el = i / STEPS;
                int st = i - el * STEPS;
                Oblk[i] = sbuf[el][st];
            }
        }
    }
}

extern "C" void kernel_launch(void* const* d_in, const int* in_sizes, int n_in,
                              void* d_out, int out_size)
{
    const float* S      = (const float*)d_in[0];
    const float* W1     = (const float*)d_in[1];
    const float* b1     = (const float*)d_in[2];
    const float* W2     = (const float*)d_in[3];
    const float* b2     = (const float*)d_in[4];
    const float* a_init = (const float*)d_in[5];
    float* out = (float*)d_out;

    int B = in_sizes[0] / STEPS;
    int grid = (B + EPC - 1) / EPC;
    rhm_kernel<<<grid, TPB>>>(S, W1, b1, W2, b2, a_init, out, B);
}